// round 6
// baseline (speedup 1.0000x reference)
#include <cuda_runtime.h>
#include <cstdint>

// 2D acoustic FDTD, 500 steps, 8 shots, 256x256, 128 recs/shot.
// One persistent kernel; shot = CSZ-CTA cluster; fields in SMEM + registers.
// Preferred: CSZ=16 (128 CTAs -> 128 SMs). Fallback: CSZ=8.

#define DT 0.001f
#define DX 10.0f

constexpr int NT   = 500;
constexpr int NS   = 8;
constexpr int NZ   = 256;
constexpr int NXC  = 256;
constexpr int NREC = 128;

constexpr int NTHREADS = 1024;
constexpr int COL4 = NXC / 4;           // 64
constexpr int RG   = NTHREADS / COL4;   // 16 row-groups

// ---------------------------------------------------------------- PTX helpers
__device__ __forceinline__ uint32_t cvta_smem(const void* p) {
    return (uint32_t)__cvta_generic_to_shared(p);
}
__device__ __forceinline__ uint32_t mapa_cluster(uint32_t laddr, uint32_t rank) {
    uint32_t r;
    asm("mapa.shared::cluster.u32 %0, %1, %2;" : "=r"(r) : "r"(laddr), "r"(rank));
    return r;
}
__device__ __forceinline__ float4 ld_dsmem_v4(uint32_t addr) {
    float4 v;
    asm volatile("ld.shared::cluster.v4.f32 {%0,%1,%2,%3}, [%4];"
                 : "=f"(v.x), "=f"(v.y), "=f"(v.z), "=f"(v.w) : "r"(addr));
    return v;
}
__device__ __forceinline__ void cluster_sync_() {
    asm volatile("barrier.cluster.arrive.aligned;" ::: "memory");
    asm volatile("barrier.cluster.wait.aligned;" ::: "memory");
}
__device__ __forceinline__ uint32_t cluster_rank_() {
    uint32_t r;
    asm("mov.u32 %0, %%cluster_ctarank;" : "=r"(r));
    return r;
}

// ---------------------------------------------------------------- kernel
template<int CSZ>
__global__ void __launch_bounds__(NTHREADS, 1)
wave_kernel(const float* __restrict__ x,     // (NT, NS)
            const float* __restrict__ vp,    // (NZ, NXC)
            const int*   __restrict__ src,   // (NS, 2)
            const int*   __restrict__ rec,   // (NS, NREC, 2)
            float*       __restrict__ out)   // (NT, NS, NREC)
{
    constexpr int ROWS = NZ / CSZ;          // 16 or 32
    constexpr int RPT  = ROWS / RG;         // 1 or 2
    constexpr int BUF_ELEMS = ROWS * NXC;

    extern __shared__ float sm[];
    float* buf0 = sm;
    float* buf1 = sm + BUF_ELEMS;
    float* xs   = sm + 2 * BUF_ELEMS;

    __shared__ int rcnt;
    __shared__ int2 rlist[NREC];

    const int tid  = threadIdx.x;
    const uint32_t rank = cluster_rank_();
    const int shot = blockIdx.x / CSZ;

    const int col4 = tid & (COL4 - 1);
    const int rg   = tid >> 6;           // 0..15
    const int lr0  = rg * RPT;
    const int xcol = col4 * 4;
    const bool has_n = (rank > 0);
    const bool has_s = (rank < CSZ - 1);

    // --- init ----------------------------------------------------------------
    for (int i = tid; i < BUF_ELEMS; i += NTHREADS) { buf0[i] = 0.f; buf1[i] = 0.f; }
    for (int i = tid; i < NT; i += NTHREADS) xs[i] = x[i * NS + shot];
    if (tid == 0) rcnt = 0;
    __syncthreads();

    // claim receivers owned by this CTA
    if (tid < NREC) {
        const int gi = shot * NREC + tid;
        const int rz = rec[gi * 2 + 0];
        const int rx = rec[gi * 2 + 1];
        if (rz / ROWS == (int)rank) {
            int s = atomicAdd(&rcnt, 1);
            rlist[s] = make_int2((rz % ROWS) * NXC + rx, shot * NREC + tid);
        }
    }

    // c2 in registers
    float4 c2r[RPT];
    const float sc = DT / DX;
#pragma unroll
    for (int j = 0; j < RPT; j++) {
        const int g = (int)rank * ROWS + lr0 + j;
        float4 v = *(const float4*)(vp + g * NXC + xcol);
        float a = v.x * sc, b = v.y * sc, c = v.z * sc, d = v.w * sc;
        c2r[j] = make_float4(a * a, b * b, c * c, d * d);
    }

    // field registers: prev and cur (zero at t=0)
    float4 pr[RPT], cC[RPT];
#pragma unroll
    for (int j = 0; j < RPT; j++) {
        pr[j] = make_float4(0.f, 0.f, 0.f, 0.f);
        cC[j] = make_float4(0.f, 0.f, 0.f, 0.f);
    }

    // source ownership
    const int sz = src[shot * 2 + 0];
    const int sx = src[shot * 2 + 1];
    const int sj = sz - ((int)rank * ROWS + lr0);
    const bool shere = (sj >= 0 && sj < RPT && sx >= xcol && sx < xcol + 4);
    const int scomp = sx - xcol;

    // DSMEM halo addresses (both parities)
    const uint32_t sa0 = cvta_smem(buf0);
    const uint32_t sa1 = cvta_smem(buf1);
    uint32_t nh0 = 0, nh1 = 0, sh0 = 0, sh1 = 0;
    if (rg == 0 && has_n) {
        const uint32_t off = (uint32_t)((ROWS - 1) * NXC + xcol) * 4u;
        nh0 = mapa_cluster(sa0 + off, rank - 1);
        nh1 = mapa_cluster(sa1 + off, rank - 1);
    }
    if (rg == RG - 1 && has_s) {
        const uint32_t off = (uint32_t)(xcol) * 4u;
        sh0 = mapa_cluster(sa0 + off, rank + 1);
        sh1 = mapa_cluster(sa1 + off, rank + 1);
    }

    __syncthreads();
    const bool samp = (tid < rcnt);
    int roff = 0;
    float* outp = out;
    if (samp) {
        int2 e = rlist[tid];
        roff = e.x;
        outp = out + e.y;
    }

    cluster_sync_();  // zeroed buffers visible cluster-wide

    // --- one FDTD step (register-resident field) -----------------------------
    auto step = [&](const float* __restrict__ cur, float* __restrict__ nxt,
                    uint32_t nh, uint32_t sh, int t) {
        const int toff = (t + 2 < NT - 1) ? t + 2 : NT - 1;
        const float amp = xs[t] + xs[toff];

        // row above the strip
        float4 vN;
        if (rg == 0) {
            vN = has_n ? ld_dsmem_v4(nh) : make_float4(0.f, 0.f, 0.f, 0.f);
        } else {
            vN = *(const float4*)(cur + (lr0 - 1) * NXC + xcol);
        }

#pragma unroll
        for (int j = 0; j < RPT; j++) {
            const int lr = lr0 + j;
            const float4 cc = cC[j];

            float4 vS;
            if (j < RPT - 1) {
                vS = cC[j + 1];
            } else if (rg == RG - 1) {
                vS = has_s ? ld_dsmem_v4(sh) : make_float4(0.f, 0.f, 0.f, 0.f);
            } else {
                vS = *(const float4*)(cur + (lr + 1) * NXC + xcol);
            }

            const float lft = (xcol > 0)       ? cur[lr * NXC + xcol - 1] : 0.f;
            const float rgt = (xcol + 4 < NXC) ? cur[lr * NXC + xcol + 4] : 0.f;

            float4 lap;
            lap.x = vN.x + vS.x + lft  + cc.y - 4.f * cc.x;
            lap.y = vN.y + vS.y + cc.x + cc.z - 4.f * cc.y;
            lap.z = vN.z + vS.z + cc.y + cc.w - 4.f * cc.z;
            lap.w = vN.w + vS.w + cc.z + rgt  - 4.f * cc.w;

            float4 nv;
            nv.x = 2.f * cc.x - pr[j].x + c2r[j].x * lap.x;
            nv.y = 2.f * cc.y - pr[j].y + c2r[j].y * lap.y;
            nv.z = 2.f * cc.z - pr[j].z + c2r[j].z * lap.z;
            nv.w = 2.f * cc.w - pr[j].w + c2r[j].w * lap.w;

            if (shere && j == sj) {
                if      (scomp == 0) nv.x += amp;
                else if (scomp == 1) nv.y += amp;
                else if (scomp == 2) nv.z += amp;
                else                 nv.w += amp;
            }

            *(float4*)(nxt + lr * NXC + xcol) = nv;
            pr[j] = cc;
            cC[j] = nv;
            vN = cc;
        }

        cluster_sync_();  // release my nxt stores, acquire everyone's

        if (samp) {
            *outp = nxt[roff];
            outp += NS * NREC;
        }
    };

    // --- main time loop, unrolled x2 for compile-time buffer parity ----------
    for (int t2 = 0; t2 < NT; t2 += 2) {
        step(buf0, buf1, nh0, sh0, t2);
        step(buf1, buf0, nh1, sh1, t2 + 1);
    }
}

// ---------------------------------------------------------------- launch
extern "C" void kernel_launch(void* const* d_in, const int* in_sizes, int n_in,
                              void* d_out, int out_size)
{
    const float* x   = (const float*)d_in[0];
    const float* vp  = (const float*)d_in[1];
    const int*   src = (const int*)d_in[2];
    const int*   rec = (const int*)d_in[3];
    float*       out = (float*)d_out;

    constexpr size_t SMEM16 = (size_t)(2 * (NZ / 16) * NXC + 512) * sizeof(float);
    constexpr size_t SMEM8  = (size_t)(2 * (NZ / 8)  * NXC + 512) * sizeof(float);

    cudaFuncSetAttribute((const void*)wave_kernel<16>,
                         cudaFuncAttributeMaxDynamicSharedMemorySize, (int)SMEM16);
    cudaFuncSetAttribute((const void*)wave_kernel<16>,
                         cudaFuncAttributeNonPortableClusterSizeAllowed, 1);
    cudaFuncSetAttribute((const void*)wave_kernel<8>,
                         cudaFuncAttributeMaxDynamicSharedMemorySize, (int)SMEM8);

    // deterministic capability probe for cluster size 16
    cudaLaunchConfig_t probe = {};
    probe.gridDim  = { NS * 16, 1, 1 };
    probe.blockDim = { NTHREADS, 1, 1 };
    probe.dynamicSmemBytes = SMEM16;
    int maxc = 0;
    cudaOccupancyMaxPotentialClusterSize(&maxc, wave_kernel<16>, &probe);

    cudaLaunchAttribute attr[1];
    attr[0].id = cudaLaunchAttributeClusterDimension;

    if (maxc >= 16) {
        cudaLaunchConfig_t cfg = {};
        cfg.gridDim  = { NS * 16, 1, 1 };
        cfg.blockDim = { NTHREADS, 1, 1 };
        cfg.dynamicSmemBytes = SMEM16;
        attr[0].val.clusterDim = { 16, 1, 1 };
        cfg.attrs = attr;
        cfg.numAttrs = 1;
        cudaLaunchKernelEx(&cfg, wave_kernel<16>, x, vp, src, rec, out);
    } else {
        cudaLaunchConfig_t cfg = {};
        cfg.gridDim  = { NS * 8, 1, 1 };
        cfg.blockDim = { NTHREADS, 1, 1 };
        cfg.dynamicSmemBytes = SMEM8;
        attr[0].val.clusterDim = { 8, 1, 1 };
        cfg.attrs = attr;
        cfg.numAttrs = 1;
        cudaLaunchKernelEx(&cfg, wave_kernel<8>, x, vp, src, rec, out);
    }
}